// round 13
// baseline (speedup 1.0000x reference)
#include <cuda_runtime.h>
#include <cuda_fp16.h>
#include <cstdint>

#define NATOMS 50000
#define NEDGES 800000
#define NTILES ((NATOMS + 127) / 128)   // 391

// scratch: per atom 96 half2 of x (MLP output), then 96 half2 of mu
__device__ __half2 g_xm[NATOMS * 192];

// ---------------------------------------------------------------------------
// helpers
// ---------------------------------------------------------------------------
__device__ __forceinline__ uint32_t smaddr(const void* p) {
    return (uint32_t)__cvta_generic_to_shared(p);
}
__device__ __forceinline__ uint32_t f2h2(float a, float b) {
    __half2 h = __floats2half2_rn(a, b);
    return *reinterpret_cast<uint32_t*>(&h);
}
__device__ __forceinline__ float silu(float v) {
    return v / (1.0f + __expf(-v));
}

// ---------------------------------------------------------------------------
// Kernel A: persistent tensor-core MLP. 148 blocks; weights staged once per
// block; each block loops over atom tiles (128 atoms each).
// sH rows are per-warp exclusive -> no block sync needed inside the tile loop.
// ---------------------------------------------------------------------------
__global__ __launch_bounds__(256) void painn_mlp_tc(
    const float* __restrict__ q,
    const float* __restrict__ W1, const float* __restrict__ b1,
    const float* __restrict__ W2, const float* __restrict__ b2)
{
    __shared__ __half sH[128 * 64];
    __shared__ __half sW1[64 * 64];
    __shared__ __half sW2[64 * 192];

    const int t = threadIdx.x;

    // stage weights once (XOR-swizzled 8-half blocks)
    for (int idx = t; idx < 64 * 16; idx += 256) {
        int r = idx >> 4, c4 = idx & 15;
        float4 v = __ldg((const float4*)W1 + r * 16 + c4);
        int blk = (c4 >> 1) ^ (r & 7);
        __half2* d = (__half2*)&sW1[r * 64 + blk * 8 + (c4 & 1) * 4];
        d[0] = __floats2half2_rn(v.x, v.y);
        d[1] = __floats2half2_rn(v.z, v.w);
    }
    for (int idx = t; idx < 64 * 48; idx += 256) {
        int r = idx / 48, c4 = idx % 48;
        float4 v = __ldg((const float4*)W2 + r * 48 + c4);
        int blk = (c4 >> 1) ^ (r & 7);
        __half2* d = (__half2*)&sW2[r * 192 + blk * 8 + (c4 & 1) * 4];
        d[0] = __floats2half2_rn(v.x, v.y);
        d[1] = __floats2half2_rn(v.z, v.w);
    }
    __syncthreads();

    const int w    = t >> 5;
    const int lane = t & 31;
    const int r    = lane >> 2;
    const int cc   = (lane & 3) * 2;
    const int lrow = lane & 15;

    for (int tile = blockIdx.x; tile < NTILES; tile += gridDim.x) {
        const int atom0 = tile * 128;

        // ---- phase 1 A fragments straight from q ----
        uint32_t A[4][4];
        {
            const int row0 = atom0 + w * 16 + r;
            const int row1 = row0 + 8;
            const bool v0 = row0 < NATOMS, v1 = row1 < NATOMS;
            const float2* q0 = (const float2*)(q + (size_t)row0 * 64);
            const float2* q1 = (const float2*)(q + (size_t)row1 * 64);
#pragma unroll
            for (int kt = 0; kt < 4; kt++) {
                int k2 = kt * 8 + (cc >> 1);
                float2 f0 = v0 ? __ldg(&q0[k2])     : make_float2(0.f, 0.f);
                float2 f1 = v1 ? __ldg(&q1[k2])     : make_float2(0.f, 0.f);
                float2 f2 = v0 ? __ldg(&q0[k2 + 4]) : make_float2(0.f, 0.f);
                float2 f3 = v1 ? __ldg(&q1[k2 + 4]) : make_float2(0.f, 0.f);
                A[kt][0] = f2h2(f0.x, f0.y);
                A[kt][1] = f2h2(f1.x, f1.y);
                A[kt][2] = f2h2(f2.x, f2.y);
                A[kt][3] = f2h2(f3.x, f3.y);
            }
        }

        // ---- phase 1: H = silu(q*W1 + b1) ----
#pragma unroll
        for (int nt = 0; nt < 8; nt++) {
            float c0 = 0.f, c1 = 0.f, c2 = 0.f, c3 = 0.f;
#pragma unroll
            for (int kt = 0; kt < 4; kt++) {
                int row = kt * 16 + lrow;
                int blk = nt ^ (row & 7);
                uint32_t addr = smaddr(&sW1[row * 64 + blk * 8]);
                uint32_t b0, b1r;
                asm volatile("ldmatrix.sync.aligned.m8n8.x2.trans.shared.b16 {%0,%1}, [%2];"
                             : "=r"(b0), "=r"(b1r) : "r"(addr));
                asm volatile("mma.sync.aligned.m16n8k16.row.col.f32.f16.f16.f32 "
                             "{%0,%1,%2,%3}, {%4,%5,%6,%7}, {%8,%9}, {%0,%1,%2,%3};"
                             : "+f"(c0), "+f"(c1), "+f"(c2), "+f"(c3)
                             : "r"(A[kt][0]), "r"(A[kt][1]), "r"(A[kt][2]), "r"(A[kt][3]),
                               "r"(b0), "r"(b1r));
            }
            int col = nt * 8 + cc;
            float bb0 = __ldg(&b1[col]), bb1 = __ldg(&b1[col + 1]);
            int hr0 = w * 16 + r, hr1 = hr0 + 8;
            int blk = nt ^ (r & 7);
            *(__half2*)&sH[hr0 * 64 + blk * 8 + cc] =
                __floats2half2_rn(silu(c0 + bb0), silu(c1 + bb1));
            *(__half2*)&sH[hr1 * 64 + blk * 8 + cc] =
                __floats2half2_rn(silu(c2 + bb0), silu(c3 + bb1));
        }
        __syncwarp();

        // ---- phase 2 A fragments from sH (own rows only) ----
        uint32_t H[4][4];
#pragma unroll
        for (int kt = 0; kt < 4; kt++) {
            int row = w * 16 + lrow;
            int blk = (kt * 2 + (lane >> 4)) ^ (row & 7);
            uint32_t addr = smaddr(&sH[row * 64 + blk * 8]);
            asm volatile("ldmatrix.sync.aligned.m8n8.x4.shared.b16 {%0,%1,%2,%3}, [%4];"
                         : "=r"(H[kt][0]), "=r"(H[kt][1]), "=r"(H[kt][2]), "=r"(H[kt][3])
                         : "r"(addr));
        }
        __syncwarp();   // sH reads done before next tile's phase-1 writes

        // ---- phase 2: x = H*W2 + b2 -> g_xm fp16 ----
        const int row0 = atom0 + w * 16 + r;
        const int row1 = row0 + 8;
#pragma unroll
        for (int nt = 0; nt < 24; nt++) {
            float c0 = 0.f, c1 = 0.f, c2 = 0.f, c3 = 0.f;
#pragma unroll
            for (int kt = 0; kt < 4; kt++) {
                int row = kt * 16 + lrow;
                int blk = nt ^ (row & 7);
                uint32_t addr = smaddr(&sW2[row * 192 + blk * 8]);
                uint32_t b0, b1r;
                asm volatile("ldmatrix.sync.aligned.m8n8.x2.trans.shared.b16 {%0,%1}, [%2];"
                             : "=r"(b0), "=r"(b1r) : "r"(addr));
                asm volatile("mma.sync.aligned.m16n8k16.row.col.f32.f16.f16.f32 "
                             "{%0,%1,%2,%3}, {%4,%5,%6,%7}, {%8,%9}, {%0,%1,%2,%3};"
                             : "+f"(c0), "+f"(c1), "+f"(c2), "+f"(c3)
                             : "r"(H[kt][0]), "r"(H[kt][1]), "r"(H[kt][2]), "r"(H[kt][3]),
                               "r"(b0), "r"(b1r));
            }
            int col = nt * 8 + cc;
            float bb0 = __ldg(&b2[col]), bb1 = __ldg(&b2[col + 1]);
            if (row0 < NATOMS)
                g_xm[(size_t)row0 * 192 + (col >> 1)] = __floats2half2_rn(c0 + bb0, c1 + bb1);
            if (row1 < NATOMS)
                g_xm[(size_t)row1 * 192 + (col >> 1)] = __floats2half2_rn(c2 + bb0, c3 + bb1);
        }
    }
}

// ---------------------------------------------------------------------------
// Fused: out = concat(q, mu)  AND  g_xm[:,96:192] = fp16(mu)
// streaming reads evict-first; out/g_xm stay L2-resident for edge phase.
// ---------------------------------------------------------------------------
__global__ __launch_bounds__(256) void init_fuse_kernel(
    const float* __restrict__ q, const float* __restrict__ mu,
    float* __restrict__ out)
{
    const int NQ2 = NATOMS * 32;
    const int NT2 = NATOMS * 128;
    int i = blockIdx.x * blockDim.x + threadIdx.x;
    if (i < NQ2) {
        ((float2*)out)[i] = __ldcs((const float2*)q + i);
    } else if (i < NT2) {
        int m = i - NQ2;
        float2 v = __ldcs((const float2*)mu + m);
        ((float2*)out)[i] = v;
        g_xm[(size_t)(m / 96) * 192 + 96 + (m % 96)] = __floats2half2_rn(v.x, v.y);
    }
}

// ---------------------------------------------------------------------------
// Kernel C: edges in original order, half-warp per edge.
// Streaming operands evict-first (__ldcs); gathers evict-normal (__ldg).
// ---------------------------------------------------------------------------
__device__ __forceinline__ void red4(float* p, float4 v) {
    asm volatile("red.global.add.v4.f32 [%0], {%1, %2, %3, %4};"
                 :: "l"(p), "f"(v.x), "f"(v.y), "f"(v.z), "f"(v.w)
                 : "memory");
}

__device__ __forceinline__ float4 h4_to_f4(uint2 u) {
    __half2 lo = *(__half2*)&u.x;
    __half2 hi = *(__half2*)&u.y;
    float2 a = __half22float2(lo);
    float2 b = __half22float2(hi);
    return make_float4(a.x, a.y, b.x, b.y);
}

__global__ __launch_bounds__(256) void painn_edge_kernel(
    const float* __restrict__ Wij, const float* __restrict__ dir_ij,
    const int* __restrict__ idx_i, const int* __restrict__ idx_j,
    float* __restrict__ out)
{
    const int warp = (blockIdx.x * blockDim.x + threadIdx.x) >> 5;
    const int lane = threadIdx.x & 31;
    const int sub = lane >> 4;
    const int sl  = lane & 15;

    const int e0 = warp * 16;
    if (e0 >= NEDGES) return;

#pragma unroll 4
    for (int e = e0 + sub; e < e0 + 16; e += 2) {
        const int i = __ldcs(&idx_i[e]);
        const int j = __ldcs(&idx_j[e]);

        const float dx = __ldcs(&dir_ij[(size_t)e * 3 + 0]);
        const float dy = __ldcs(&dir_ij[(size_t)e * 3 + 1]);
        const float dz = __ldcs(&dir_ij[(size_t)e * 3 + 2]);

        const float4* W4 = (const float4*)(Wij + (size_t)e * 192);
        const uint2* T = (const uint2*)(g_xm + (size_t)j * 192);

        const float4 w0 = __ldcs(&W4[sl]);
        const float4 w1 = __ldcs(&W4[16 + sl]);
        const float4 w2 = __ldcs(&W4[32 + sl]);
        const float4 x0 = h4_to_f4(__ldg(&T[sl]));
        const float4 x1 = h4_to_f4(__ldg(&T[16 + sl]));
        const float4 x2 = h4_to_f4(__ldg(&T[32 + sl]));
        const float4 m0 = h4_to_f4(__ldg(&T[48 + sl]));
        const float4 m1 = h4_to_f4(__ldg(&T[64 + sl]));
        const float4 m2 = h4_to_f4(__ldg(&T[80 + sl]));

        float4 dq;
        dq.x = w0.x * x0.x; dq.y = w0.y * x0.y;
        dq.z = w0.z * x0.z; dq.w = w0.w * x0.w;

        const float4 mR = make_float4(w1.x * x1.x, w1.y * x1.y, w1.z * x1.z, w1.w * x1.w);
        const float4 mM = make_float4(w2.x * x2.x, w2.y * x2.y, w2.z * x2.z, w2.w * x2.w);

        float4 d0, d1, d2;
        d0.x = fmaf(mR.x, dx, mM.x * m0.x); d0.y = fmaf(mR.y, dx, mM.y * m0.y);
        d0.z = fmaf(mR.z, dx, mM.z * m0.z); d0.w = fmaf(mR.w, dx, mM.w * m0.w);
        d1.x = fmaf(mR.x, dy, mM.x * m1.x); d1.y = fmaf(mR.y, dy, mM.y * m1.y);
        d1.z = fmaf(mR.z, dy, mM.z * m1.z); d1.w = fmaf(mR.w, dy, mM.w * m1.w);
        d2.x = fmaf(mR.x, dz, mM.x * m2.x); d2.y = fmaf(mR.y, dz, mM.y * m2.y);
        d2.z = fmaf(mR.z, dz, mM.z * m2.z); d2.w = fmaf(mR.w, dz, mM.w * m2.w);

        red4(out + (size_t)i * 64 + sl * 4, dq);
        float* om = out + (size_t)NATOMS * 64 + (size_t)i * 192 + sl * 4;
        red4(om,       d0);
        red4(om + 64,  d1);
        red4(om + 128, d2);
    }
}

// ---------------------------------------------------------------------------
// launch
// ---------------------------------------------------------------------------
extern "C" void kernel_launch(void* const* d_in, const int* in_sizes, int n_in,
                              void* d_out, int out_size)
{
    int iq = -1, imu = -1, iW = -1, idir = -1, ii = -1, ij = -1;
    int iW1 = -1, ib1 = -1, iW2 = -1, ib2 = -1;
    for (int k = 0; k < n_in; k++) {
        long s = in_sizes[k];
        if      (s == (long)NATOMS * 64)   iq  = k;
        else if (s == (long)NATOMS * 192)  imu = k;
        else if (s == (long)NEDGES * 192)  iW  = k;
        else if (s == (long)NEDGES * 3)    idir = k;
        else if (s == (long)NEDGES)        { if (ii < 0) ii = k; else ij = k; }
        else if (s == 64 * 64)             iW1 = k;
        else if (s == 64)                  ib1 = k;
        else if (s == 64 * 192)            iW2 = k;
        else if (s == 192)                 ib2 = k;
    }

    const float* q   = (const float*)d_in[iq];
    const float* mu  = (const float*)d_in[imu];
    const float* Wij = (const float*)d_in[iW];
    const float* dir = (const float*)d_in[idir];
    const int*  idxi = (const int*)d_in[ii];
    const int*  idxj = (const int*)d_in[ij];
    const float* W1  = (const float*)d_in[iW1];
    const float* b1  = (const float*)d_in[ib1];
    const float* W2  = (const float*)d_in[iW2];
    const float* b2  = (const float*)d_in[ib2];
    float* out = (float*)d_out;

    // persistent tensor-core MLP -> fp16 x part of g_xm
    painn_mlp_tc<<<148, 256>>>(q, W1, b1, W2, b2);

    // out = concat(q, mu) + fp16 mu table
    {
        const int total2 = NATOMS * 128;
        init_fuse_kernel<<<(total2 + 255) / 256, 256>>>(q, mu, out);
    }

    // edge scatter in original order (16 edges per warp)
    {
        const int warps = (NEDGES + 15) / 16;
        const int blocks = (warps * 32 + 255) / 256;
        painn_edge_kernel<<<blocks, 256>>>(Wij, dir, idxi, idxj, out);
    }
}

// round 14
// speedup vs baseline: 1.0595x; 1.0595x over previous
#include <cuda_runtime.h>
#include <cuda_fp16.h>
#include <cstdint>

#define NATOMS 50000
#define NEDGES 800000

// scratch: per atom 96 half2 of x (MLP output), then 96 half2 of mu
__device__ __half2 g_xm[NATOMS * 192];

// ---------------------------------------------------------------------------
// helpers
// ---------------------------------------------------------------------------
__device__ __forceinline__ uint32_t smaddr(const void* p) {
    return (uint32_t)__cvta_generic_to_shared(p);
}
__device__ __forceinline__ uint32_t f2h2(float a, float b) {
    __half2 h = __floats2half2_rn(a, b);
    return *reinterpret_cast<uint32_t*>(&h);
}
__device__ __forceinline__ float silu(float v) {
    return v / (1.0f + __expf(-v));
}

// ---------------------------------------------------------------------------
// Kernel A: per-atom MLP on tensor cores (R12 winning config, grid 391).
// ---------------------------------------------------------------------------
__global__ __launch_bounds__(256) void painn_mlp_tc(
    const float* __restrict__ q,
    const float* __restrict__ W1, const float* __restrict__ b1,
    const float* __restrict__ W2, const float* __restrict__ b2)
{
    __shared__ __half sH[128 * 64];
    __shared__ __half sW1[64 * 64];
    __shared__ __half sW2[64 * 192];

    const int t = threadIdx.x;
    const int atom0 = blockIdx.x * 128;

    for (int idx = t; idx < 64 * 16; idx += 256) {
        int r = idx >> 4, c4 = idx & 15;
        float4 v = __ldg((const float4*)W1 + r * 16 + c4);
        int blk = (c4 >> 1) ^ (r & 7);
        __half2* d = (__half2*)&sW1[r * 64 + blk * 8 + (c4 & 1) * 4];
        d[0] = __floats2half2_rn(v.x, v.y);
        d[1] = __floats2half2_rn(v.z, v.w);
    }
    for (int idx = t; idx < 64 * 48; idx += 256) {
        int r = idx / 48, c4 = idx % 48;
        float4 v = __ldg((const float4*)W2 + r * 48 + c4);
        int blk = (c4 >> 1) ^ (r & 7);
        __half2* d = (__half2*)&sW2[r * 192 + blk * 8 + (c4 & 1) * 4];
        d[0] = __floats2half2_rn(v.x, v.y);
        d[1] = __floats2half2_rn(v.z, v.w);
    }
    __syncthreads();

    const int w    = t >> 5;
    const int lane = t & 31;
    const int r    = lane >> 2;
    const int cc   = (lane & 3) * 2;

    uint32_t A[4][4];
    {
        const int row0 = atom0 + w * 16 + r;
        const int row1 = row0 + 8;
        const bool v0 = row0 < NATOMS, v1 = row1 < NATOMS;
        const float2* q0 = (const float2*)(q + (size_t)row0 * 64);
        const float2* q1 = (const float2*)(q + (size_t)row1 * 64);
#pragma unroll
        for (int kt = 0; kt < 4; kt++) {
            int k2 = kt * 8 + (cc >> 1);
            float2 f0 = v0 ? __ldg(&q0[k2])     : make_float2(0.f, 0.f);
            float2 f1 = v1 ? __ldg(&q1[k2])     : make_float2(0.f, 0.f);
            float2 f2 = v0 ? __ldg(&q0[k2 + 4]) : make_float2(0.f, 0.f);
            float2 f3 = v1 ? __ldg(&q1[k2 + 4]) : make_float2(0.f, 0.f);
            A[kt][0] = f2h2(f0.x, f0.y);
            A[kt][1] = f2h2(f1.x, f1.y);
            A[kt][2] = f2h2(f2.x, f2.y);
            A[kt][3] = f2h2(f3.x, f3.y);
        }
    }

    const int lrow = lane & 15;
#pragma unroll
    for (int nt = 0; nt < 8; nt++) {
        float c0 = 0.f, c1 = 0.f, c2 = 0.f, c3 = 0.f;
#pragma unroll
        for (int kt = 0; kt < 4; kt++) {
            int row = kt * 16 + lrow;
            int blk = nt ^ (row & 7);
            uint32_t addr = smaddr(&sW1[row * 64 + blk * 8]);
            uint32_t b0, b1r;
            asm volatile("ldmatrix.sync.aligned.m8n8.x2.trans.shared.b16 {%0,%1}, [%2];"
                         : "=r"(b0), "=r"(b1r) : "r"(addr));
            asm volatile("mma.sync.aligned.m16n8k16.row.col.f32.f16.f16.f32 "
                         "{%0,%1,%2,%3}, {%4,%5,%6,%7}, {%8,%9}, {%0,%1,%2,%3};"
                         : "+f"(c0), "+f"(c1), "+f"(c2), "+f"(c3)
                         : "r"(A[kt][0]), "r"(A[kt][1]), "r"(A[kt][2]), "r"(A[kt][3]),
                           "r"(b0), "r"(b1r));
        }
        int col = nt * 8 + cc;
        float bb0 = __ldg(&b1[col]), bb1 = __ldg(&b1[col + 1]);
        int hr0 = w * 16 + r, hr1 = hr0 + 8;
        int blk = nt ^ (r & 7);
        *(__half2*)&sH[hr0 * 64 + blk * 8 + cc] =
            __floats2half2_rn(silu(c0 + bb0), silu(c1 + bb1));
        *(__half2*)&sH[hr1 * 64 + blk * 8 + cc] =
            __floats2half2_rn(silu(c2 + bb0), silu(c3 + bb1));
    }
    __syncwarp();

    uint32_t H[4][4];
#pragma unroll
    for (int kt = 0; kt < 4; kt++) {
        int row = w * 16 + lrow;
        int blk = (kt * 2 + (lane >> 4)) ^ (row & 7);
        uint32_t addr = smaddr(&sH[row * 64 + blk * 8]);
        asm volatile("ldmatrix.sync.aligned.m8n8.x4.shared.b16 {%0,%1,%2,%3}, [%4];"
                     : "=r"(H[kt][0]), "=r"(H[kt][1]), "=r"(H[kt][2]), "=r"(H[kt][3])
                     : "r"(addr));
    }

    const int row0 = atom0 + w * 16 + r;
    const int row1 = row0 + 8;
#pragma unroll
    for (int nt = 0; nt < 24; nt++) {
        float c0 = 0.f, c1 = 0.f, c2 = 0.f, c3 = 0.f;
#pragma unroll
        for (int kt = 0; kt < 4; kt++) {
            int row = kt * 16 + lrow;
            int blk = nt ^ (row & 7);
            uint32_t addr = smaddr(&sW2[row * 192 + blk * 8]);
            uint32_t b0, b1r;
            asm volatile("ldmatrix.sync.aligned.m8n8.x2.trans.shared.b16 {%0,%1}, [%2];"
                         : "=r"(b0), "=r"(b1r) : "r"(addr));
            asm volatile("mma.sync.aligned.m16n8k16.row.col.f32.f16.f16.f32 "
                         "{%0,%1,%2,%3}, {%4,%5,%6,%7}, {%8,%9}, {%0,%1,%2,%3};"
                         : "+f"(c0), "+f"(c1), "+f"(c2), "+f"(c3)
                         : "r"(H[kt][0]), "r"(H[kt][1]), "r"(H[kt][2]), "r"(H[kt][3]),
                           "r"(b0), "r"(b1r));
        }
        int col = nt * 8 + cc;
        float bb0 = __ldg(&b2[col]), bb1 = __ldg(&b2[col + 1]);
        if (row0 < NATOMS)
            g_xm[(size_t)row0 * 192 + (col >> 1)] = __floats2half2_rn(c0 + bb0, c1 + bb1);
        if (row1 < NATOMS)
            g_xm[(size_t)row1 * 192 + (col >> 1)] = __floats2half2_rn(c2 + bb0, c3 + bb1);
    }
}

// ---------------------------------------------------------------------------
// Fused: out = concat(q, mu)  AND  g_xm[:,96:192] = fp16(mu)
// streaming reads evict-first; out/g_xm stay L2-resident for edge phase.
// ---------------------------------------------------------------------------
__global__ __launch_bounds__(256) void init_fuse_kernel(
    const float* __restrict__ q, const float* __restrict__ mu,
    float* __restrict__ out)
{
    const int NQ2 = NATOMS * 32;
    const int NT2 = NATOMS * 128;
    int i = blockIdx.x * blockDim.x + threadIdx.x;
    if (i < NQ2) {
        ((float2*)out)[i] = __ldcs((const float2*)q + i);
    } else if (i < NT2) {
        int m = i - NQ2;
        float2 v = __ldcs((const float2*)mu + m);
        ((float2*)out)[i] = v;
        g_xm[(size_t)(m / 96) * 192 + 96 + (m % 96)] = __floats2half2_rn(v.x, v.y);
    }
}

// ---------------------------------------------------------------------------
// Kernel C: edges in original order, half-warp per edge.
// Streaming operands evict-first (__ldcs); gathers evict-normal (__ldg).
// ---------------------------------------------------------------------------
__device__ __forceinline__ void red4(float* p, float4 v) {
    asm volatile("red.global.add.v4.f32 [%0], {%1, %2, %3, %4};"
                 :: "l"(p), "f"(v.x), "f"(v.y), "f"(v.z), "f"(v.w)
                 : "memory");
}

__device__ __forceinline__ float4 h4_to_f4(uint2 u) {
    __half2 lo = *(__half2*)&u.x;
    __half2 hi = *(__half2*)&u.y;
    float2 a = __half22float2(lo);
    float2 b = __half22float2(hi);
    return make_float4(a.x, a.y, b.x, b.y);
}

__global__ __launch_bounds__(256) void painn_edge_kernel(
    const float* __restrict__ Wij, const float* __restrict__ dir_ij,
    const int* __restrict__ idx_i, const int* __restrict__ idx_j,
    float* __restrict__ out)
{
    const int warp = (blockIdx.x * blockDim.x + threadIdx.x) >> 5;
    const int lane = threadIdx.x & 31;
    const int sub = lane >> 4;
    const int sl  = lane & 15;

    const int e0 = warp * 16;
    if (e0 >= NEDGES) return;

#pragma unroll 4
    for (int e = e0 + sub; e < e0 + 16; e += 2) {
        const int i = __ldcs(&idx_i[e]);
        const int j = __ldcs(&idx_j[e]);

        const float dx = __ldcs(&dir_ij[(size_t)e * 3 + 0]);
        const float dy = __ldcs(&dir_ij[(size_t)e * 3 + 1]);
        const float dz = __ldcs(&dir_ij[(size_t)e * 3 + 2]);

        const float4* W4 = (const float4*)(Wij + (size_t)e * 192);
        const uint2* T = (const uint2*)(g_xm + (size_t)j * 192);

        const float4 w0 = __ldcs(&W4[sl]);
        const float4 w1 = __ldcs(&W4[16 + sl]);
        const float4 w2 = __ldcs(&W4[32 + sl]);
        const float4 x0 = h4_to_f4(__ldg(&T[sl]));
        const float4 x1 = h4_to_f4(__ldg(&T[16 + sl]));
        const float4 x2 = h4_to_f4(__ldg(&T[32 + sl]));
        const float4 m0 = h4_to_f4(__ldg(&T[48 + sl]));
        const float4 m1 = h4_to_f4(__ldg(&T[64 + sl]));
        const float4 m2 = h4_to_f4(__ldg(&T[80 + sl]));

        float4 dq;
        dq.x = w0.x * x0.x; dq.y = w0.y * x0.y;
        dq.z = w0.z * x0.z; dq.w = w0.w * x0.w;

        const float4 mR = make_float4(w1.x * x1.x, w1.y * x1.y, w1.z * x1.z, w1.w * x1.w);
        const float4 mM = make_float4(w2.x * x2.x, w2.y * x2.y, w2.z * x2.z, w2.w * x2.w);

        float4 d0, d1, d2;
        d0.x = fmaf(mR.x, dx, mM.x * m0.x); d0.y = fmaf(mR.y, dx, mM.y * m0.y);
        d0.z = fmaf(mR.z, dx, mM.z * m0.z); d0.w = fmaf(mR.w, dx, mM.w * m0.w);
        d1.x = fmaf(mR.x, dy, mM.x * m1.x); d1.y = fmaf(mR.y, dy, mM.y * m1.y);
        d1.z = fmaf(mR.z, dy, mM.z * m1.z); d1.w = fmaf(mR.w, dy, mM.w * m1.w);
        d2.x = fmaf(mR.x, dz, mM.x * m2.x); d2.y = fmaf(mR.y, dz, mM.y * m2.y);
        d2.z = fmaf(mR.z, dz, mM.z * m2.z); d2.w = fmaf(mR.w, dz, mM.w * m2.w);

        red4(out + (size_t)i * 64 + sl * 4, dq);
        float* om = out + (size_t)NATOMS * 64 + (size_t)i * 192 + sl * 4;
        red4(om,       d0);
        red4(om + 64,  d1);
        red4(om + 128, d2);
    }
}

// ---------------------------------------------------------------------------
// launch
// ---------------------------------------------------------------------------
extern "C" void kernel_launch(void* const* d_in, const int* in_sizes, int n_in,
                              void* d_out, int out_size)
{
    int iq = -1, imu = -1, iW = -1, idir = -1, ii = -1, ij = -1;
    int iW1 = -1, ib1 = -1, iW2 = -1, ib2 = -1;
    for (int k = 0; k < n_in; k++) {
        long s = in_sizes[k];
        if      (s == (long)NATOMS * 64)   iq  = k;
        else if (s == (long)NATOMS * 192)  imu = k;
        else if (s == (long)NEDGES * 192)  iW  = k;
        else if (s == (long)NEDGES * 3)    idir = k;
        else if (s == (long)NEDGES)        { if (ii < 0) ii = k; else ij = k; }
        else if (s == 64 * 64)             iW1 = k;
        else if (s == 64)                  ib1 = k;
        else if (s == 64 * 192)            iW2 = k;
        else if (s == 192)                 ib2 = k;
    }

    const float* q   = (const float*)d_in[iq];
    const float* mu  = (const float*)d_in[imu];
    const float* Wij = (const float*)d_in[iW];
    const float* dir = (const float*)d_in[idir];
    const int*  idxi = (const int*)d_in[ii];
    const int*  idxj = (const int*)d_in[ij];
    const float* W1  = (const float*)d_in[iW1];
    const float* b1  = (const float*)d_in[ib1];
    const float* W2  = (const float*)d_in[iW2];
    const float* b2  = (const float*)d_in[ib2];
    float* out = (float*)d_out;

    // per-atom MLP on tensor cores (grid 391) -> fp16 x part of g_xm
    painn_mlp_tc<<<(NATOMS + 127) / 128, 256>>>(q, W1, b1, W2, b2);

    // out = concat(q, mu) + fp16 mu table
    {
        const int total2 = NATOMS * 128;
        init_fuse_kernel<<<(total2 + 255) / 256, 256>>>(q, mu, out);
    }

    // edge scatter in original order (16 edges per warp)
    {
        const int warps = (NEDGES + 15) / 16;
        const int blocks = (warps * 32 + 255) / 256;
        painn_edge_kernel<<<blocks, 256>>>(Wij, dir, idxi, idxj, out);
    }
}

// round 15
// speedup vs baseline: 1.0615x; 1.0019x over previous
#include <cuda_runtime.h>
#include <cuda_fp16.h>
#include <cstdint>

#define NATOMS 50000
#define NEDGES 800000
#define NT_MLP ((NATOMS + 127) / 128)   // 391 MLP blocks
#define NB_INIT 1609                     // init blocks (grid-stride)
#define NB_TOTAL (NT_MLP + NB_INIT)      // 2000

// scratch: per atom 96 half2 of x (MLP output), then 96 half2 of mu
__device__ __half2 g_xm[NATOMS * 192];

// ---------------------------------------------------------------------------
// helpers
// ---------------------------------------------------------------------------
__device__ __forceinline__ uint32_t smaddr(const void* p) {
    return (uint32_t)__cvta_generic_to_shared(p);
}
__device__ __forceinline__ uint32_t f2h2(float a, float b) {
    __half2 h = __floats2half2_rn(a, b);
    return *reinterpret_cast<uint32_t*>(&h);
}
__device__ __forceinline__ float silu(float v) {
    return v / (1.0f + __expf(-v));
}

// ---------------------------------------------------------------------------
// Fused kernel A+B: blocks [0, NT_MLP) run the tensor-core MLP;
// blocks [NT_MLP, NB_TOTAL) run out=concat(q,mu) + fp16(mu) table (grid-stride).
// The two roles are independent and resource-complementary (TC vs bandwidth).
// ---------------------------------------------------------------------------
__global__ __launch_bounds__(256) void painn_mlp_init_fused(
    const float* __restrict__ q,
    const float* __restrict__ W1, const float* __restrict__ b1,
    const float* __restrict__ W2, const float* __restrict__ b2,
    const float* __restrict__ mu, float* __restrict__ out)
{
    __shared__ __half sH[128 * 64];
    __shared__ __half sW1[64 * 64];
    __shared__ __half sW2[64 * 192];

    const int t = threadIdx.x;

    if (blockIdx.x >= NT_MLP) {
        // ---------------- init role ----------------
        const int NQ2 = NATOMS * 32;
        const int NT2 = NATOMS * 128;
        const int stride = NB_INIT * 256;
        for (int i = (blockIdx.x - NT_MLP) * 256 + t; i < NT2; i += stride) {
            if (i < NQ2) {
                ((float2*)out)[i] = __ldcs((const float2*)q + i);
            } else {
                int m = i - NQ2;
                float2 v = __ldcs((const float2*)mu + m);
                ((float2*)out)[i] = v;
                g_xm[(size_t)(m / 96) * 192 + 96 + (m % 96)] = __floats2half2_rn(v.x, v.y);
            }
        }
        return;
    }

    // ---------------- MLP role ----------------
    const int atom0 = blockIdx.x * 128;

    for (int idx = t; idx < 64 * 16; idx += 256) {
        int r = idx >> 4, c4 = idx & 15;
        float4 v = __ldg((const float4*)W1 + r * 16 + c4);
        int blk = (c4 >> 1) ^ (r & 7);
        __half2* d = (__half2*)&sW1[r * 64 + blk * 8 + (c4 & 1) * 4];
        d[0] = __floats2half2_rn(v.x, v.y);
        d[1] = __floats2half2_rn(v.z, v.w);
    }
    for (int idx = t; idx < 64 * 48; idx += 256) {
        int r = idx / 48, c4 = idx % 48;
        float4 v = __ldg((const float4*)W2 + r * 48 + c4);
        int blk = (c4 >> 1) ^ (r & 7);
        __half2* d = (__half2*)&sW2[r * 192 + blk * 8 + (c4 & 1) * 4];
        d[0] = __floats2half2_rn(v.x, v.y);
        d[1] = __floats2half2_rn(v.z, v.w);
    }
    __syncthreads();

    const int w    = t >> 5;
    const int lane = t & 31;
    const int r    = lane >> 2;
    const int cc   = (lane & 3) * 2;

    uint32_t A[4][4];
    {
        const int row0 = atom0 + w * 16 + r;
        const int row1 = row0 + 8;
        const bool v0 = row0 < NATOMS, v1 = row1 < NATOMS;
        const float2* q0 = (const float2*)(q + (size_t)row0 * 64);
        const float2* q1 = (const float2*)(q + (size_t)row1 * 64);
#pragma unroll
        for (int kt = 0; kt < 4; kt++) {
            int k2 = kt * 8 + (cc >> 1);
            float2 f0 = v0 ? __ldg(&q0[k2])     : make_float2(0.f, 0.f);
            float2 f1 = v1 ? __ldg(&q1[k2])     : make_float2(0.f, 0.f);
            float2 f2 = v0 ? __ldg(&q0[k2 + 4]) : make_float2(0.f, 0.f);
            float2 f3 = v1 ? __ldg(&q1[k2 + 4]) : make_float2(0.f, 0.f);
            A[kt][0] = f2h2(f0.x, f0.y);
            A[kt][1] = f2h2(f1.x, f1.y);
            A[kt][2] = f2h2(f2.x, f2.y);
            A[kt][3] = f2h2(f3.x, f3.y);
        }
    }

    const int lrow = lane & 15;
#pragma unroll
    for (int nt = 0; nt < 8; nt++) {
        float c0 = 0.f, c1 = 0.f, c2 = 0.f, c3 = 0.f;
#pragma unroll
        for (int kt = 0; kt < 4; kt++) {
            int row = kt * 16 + lrow;
            int blk = nt ^ (row & 7);
            uint32_t addr = smaddr(&sW1[row * 64 + blk * 8]);
            uint32_t b0, b1r;
            asm volatile("ldmatrix.sync.aligned.m8n8.x2.trans.shared.b16 {%0,%1}, [%2];"
                         : "=r"(b0), "=r"(b1r) : "r"(addr));
            asm volatile("mma.sync.aligned.m16n8k16.row.col.f32.f16.f16.f32 "
                         "{%0,%1,%2,%3}, {%4,%5,%6,%7}, {%8,%9}, {%0,%1,%2,%3};"
                         : "+f"(c0), "+f"(c1), "+f"(c2), "+f"(c3)
                         : "r"(A[kt][0]), "r"(A[kt][1]), "r"(A[kt][2]), "r"(A[kt][3]),
                           "r"(b0), "r"(b1r));
        }
        int col = nt * 8 + cc;
        float bb0 = __ldg(&b1[col]), bb1 = __ldg(&b1[col + 1]);
        int hr0 = w * 16 + r, hr1 = hr0 + 8;
        int blk = nt ^ (r & 7);
        *(__half2*)&sH[hr0 * 64 + blk * 8 + cc] =
            __floats2half2_rn(silu(c0 + bb0), silu(c1 + bb1));
        *(__half2*)&sH[hr1 * 64 + blk * 8 + cc] =
            __floats2half2_rn(silu(c2 + bb0), silu(c3 + bb1));
    }
    __syncwarp();

    uint32_t H[4][4];
#pragma unroll
    for (int kt = 0; kt < 4; kt++) {
        int row = w * 16 + lrow;
        int blk = (kt * 2 + (lane >> 4)) ^ (row & 7);
        uint32_t addr = smaddr(&sH[row * 64 + blk * 8]);
        asm volatile("ldmatrix.sync.aligned.m8n8.x4.shared.b16 {%0,%1,%2,%3}, [%4];"
                     : "=r"(H[kt][0]), "=r"(H[kt][1]), "=r"(H[kt][2]), "=r"(H[kt][3])
                     : "r"(addr));
    }

    const int row0 = atom0 + w * 16 + r;
    const int row1 = row0 + 8;
#pragma unroll
    for (int nt = 0; nt < 24; nt++) {
        float c0 = 0.f, c1 = 0.f, c2 = 0.f, c3 = 0.f;
#pragma unroll
        for (int kt = 0; kt < 4; kt++) {
            int row = kt * 16 + lrow;
            int blk = nt ^ (row & 7);
            uint32_t addr = smaddr(&sW2[row * 192 + blk * 8]);
            uint32_t b0, b1r;
            asm volatile("ldmatrix.sync.aligned.m8n8.x2.trans.shared.b16 {%0,%1}, [%2];"
                         : "=r"(b0), "=r"(b1r) : "r"(addr));
            asm volatile("mma.sync.aligned.m16n8k16.row.col.f32.f16.f16.f32 "
                         "{%0,%1,%2,%3}, {%4,%5,%6,%7}, {%8,%9}, {%0,%1,%2,%3};"
                         : "+f"(c0), "+f"(c1), "+f"(c2), "+f"(c3)
                         : "r"(H[kt][0]), "r"(H[kt][1]), "r"(H[kt][2]), "r"(H[kt][3]),
                           "r"(b0), "r"(b1r));
        }
        int col = nt * 8 + cc;
        float bb0 = __ldg(&b2[col]), bb1 = __ldg(&b2[col + 1]);
        if (row0 < NATOMS)
            g_xm[(size_t)row0 * 192 + (col >> 1)] = __floats2half2_rn(c0 + bb0, c1 + bb1);
        if (row1 < NATOMS)
            g_xm[(size_t)row1 * 192 + (col >> 1)] = __floats2half2_rn(c2 + bb0, c3 + bb1);
    }
}

// ---------------------------------------------------------------------------
// Kernel C: edges in original order, half-warp per edge.
// Streaming operands evict-first (__ldcs); gathers evict-normal (__ldg).
// ---------------------------------------------------------------------------
__device__ __forceinline__ void red4(float* p, float4 v) {
    asm volatile("red.global.add.v4.f32 [%0], {%1, %2, %3, %4};"
                 :: "l"(p), "f"(v.x), "f"(v.y), "f"(v.z), "f"(v.w)
                 : "memory");
}

__device__ __forceinline__ float4 h4_to_f4(uint2 u) {
    __half2 lo = *(__half2*)&u.x;
    __half2 hi = *(__half2*)&u.y;
    float2 a = __half22float2(lo);
    float2 b = __half22float2(hi);
    return make_float4(a.x, a.y, b.x, b.y);
}

__global__ __launch_bounds__(256) void painn_edge_kernel(
    const float* __restrict__ Wij, const float* __restrict__ dir_ij,
    const int* __restrict__ idx_i, const int* __restrict__ idx_j,
    float* __restrict__ out)
{
    const int warp = (blockIdx.x * blockDim.x + threadIdx.x) >> 5;
    const int lane = threadIdx.x & 31;
    const int sub = lane >> 4;
    const int sl  = lane & 15;

    const int e0 = warp * 16;
    if (e0 >= NEDGES) return;

#pragma unroll 4
    for (int e = e0 + sub; e < e0 + 16; e += 2) {
        const int i = __ldcs(&idx_i[e]);
        const int j = __ldcs(&idx_j[e]);

        const float dx = __ldcs(&dir_ij[(size_t)e * 3 + 0]);
        const float dy = __ldcs(&dir_ij[(size_t)e * 3 + 1]);
        const float dz = __ldcs(&dir_ij[(size_t)e * 3 + 2]);

        const float4* W4 = (const float4*)(Wij + (size_t)e * 192);
        const uint2* T = (const uint2*)(g_xm + (size_t)j * 192);

        const float4 w0 = __ldcs(&W4[sl]);
        const float4 w1 = __ldcs(&W4[16 + sl]);
        const float4 w2 = __ldcs(&W4[32 + sl]);
        const float4 x0 = h4_to_f4(__ldg(&T[sl]));
        const float4 x1 = h4_to_f4(__ldg(&T[16 + sl]));
        const float4 x2 = h4_to_f4(__ldg(&T[32 + sl]));
        const float4 m0 = h4_to_f4(__ldg(&T[48 + sl]));
        const float4 m1 = h4_to_f4(__ldg(&T[64 + sl]));
        const float4 m2 = h4_to_f4(__ldg(&T[80 + sl]));

        float4 dq;
        dq.x = w0.x * x0.x; dq.y = w0.y * x0.y;
        dq.z = w0.z * x0.z; dq.w = w0.w * x0.w;

        const float4 mR = make_float4(w1.x * x1.x, w1.y * x1.y, w1.z * x1.z, w1.w * x1.w);
        const float4 mM = make_float4(w2.x * x2.x, w2.y * x2.y, w2.z * x2.z, w2.w * x2.w);

        float4 d0, d1, d2;
        d0.x = fmaf(mR.x, dx, mM.x * m0.x); d0.y = fmaf(mR.y, dx, mM.y * m0.y);
        d0.z = fmaf(mR.z, dx, mM.z * m0.z); d0.w = fmaf(mR.w, dx, mM.w * m0.w);
        d1.x = fmaf(mR.x, dy, mM.x * m1.x); d1.y = fmaf(mR.y, dy, mM.y * m1.y);
        d1.z = fmaf(mR.z, dy, mM.z * m1.z); d1.w = fmaf(mR.w, dy, mM.w * m1.w);
        d2.x = fmaf(mR.x, dz, mM.x * m2.x); d2.y = fmaf(mR.y, dz, mM.y * m2.y);
        d2.z = fmaf(mR.z, dz, mM.z * m2.z); d2.w = fmaf(mR.w, dz, mM.w * m2.w);

        red4(out + (size_t)i * 64 + sl * 4, dq);
        float* om = out + (size_t)NATOMS * 64 + (size_t)i * 192 + sl * 4;
        red4(om,       d0);
        red4(om + 64,  d1);
        red4(om + 128, d2);
    }
}

// ---------------------------------------------------------------------------
// launch
// ---------------------------------------------------------------------------
extern "C" void kernel_launch(void* const* d_in, const int* in_sizes, int n_in,
                              void* d_out, int out_size)
{
    int iq = -1, imu = -1, iW = -1, idir = -1, ii = -1, ij = -1;
    int iW1 = -1, ib1 = -1, iW2 = -1, ib2 = -1;
    for (int k = 0; k < n_in; k++) {
        long s = in_sizes[k];
        if      (s == (long)NATOMS * 64)   iq  = k;
        else if (s == (long)NATOMS * 192)  imu = k;
        else if (s == (long)NEDGES * 192)  iW  = k;
        else if (s == (long)NEDGES * 3)    idir = k;
        else if (s == (long)NEDGES)        { if (ii < 0) ii = k; else ij = k; }
        else if (s == 64 * 64)             iW1 = k;
        else if (s == 64)                  ib1 = k;
        else if (s == 64 * 192)            iW2 = k;
        else if (s == 192)                 ib2 = k;
    }

    const float* q   = (const float*)d_in[iq];
    const float* mu  = (const float*)d_in[imu];
    const float* Wij = (const float*)d_in[iW];
    const float* dir = (const float*)d_in[idir];
    const int*  idxi = (const int*)d_in[ii];
    const int*  idxj = (const int*)d_in[ij];
    const float* W1  = (const float*)d_in[iW1];
    const float* b1  = (const float*)d_in[ib1];
    const float* W2  = (const float*)d_in[iW2];
    const float* b2  = (const float*)d_in[ib2];
    float* out = (float*)d_out;

    // fused: tensor-core MLP (blocks 0..390) + init out/mu table (blocks 391..1999)
    painn_mlp_init_fused<<<NB_TOTAL, 256>>>(q, W1, b1, W2, b2, mu, out);

    // edge scatter in original order (16 edges per warp)
    {
        const int warps = (NEDGES + 15) / 16;
        const int blocks = (warps * 32 + 255) / 256;
        painn_edge_kernel<<<blocks, 256>>>(Wij, dir, idxi, idxj, out);
    }
}